// round 13
// baseline (speedup 1.0000x reference)
#include <cuda_runtime.h>
#include <cuda_pipeline_primitives.h>

#define B 256
#define S 512
#define T 128
#define STARTT 125
#define STOPT 126
#define TB_PITCH 132  // padded row pitch (floats) for smem transT

// 64MB part-history scratch: hist[b][s][t]
__device__ float g_hist[(size_t)B * S * T];

// ---------------------------------------------------------------------------
// Kernel 1: forward Viterbi max-plus recurrence. TWO batches per 256-thread
// block -> grid 128 <= 148 SMs -> exactly one block per SM, uniform
// 2 warps/SMSP on every SM (R12 had 108 SMs with 2 blocks + 40 with 1:
// the 2-block SMs set the wall). Thread (h,j) handles to-state j of batch
// 2*blockIdx.x + h, trans column j in 128 registers.
// ---------------------------------------------------------------------------
__global__ __launch_bounds__(256, 1) void k_forward(
    const float* __restrict__ feats, const float* __restrict__ trans) {
    const int h = threadIdx.x >> 7;          // sub-batch 0/1
    const int j = threadIdx.x & 127;         // to-state
    const int b = blockIdx.x * 2 + h;

    float c[T];
#pragma unroll
    for (int i = 0; i < T; i++) c[i] = trans[i * T + j];

    __shared__ __align__(16) float part[2][2][T];  // [buf][sub-batch][state]

    const float* fb = feats + (size_t)b * S * T;
    float* hb = g_hist + (size_t)b * S * T;

    float p0 = fb[j] + c[STARTT];
    part[0][h][j] = p0;
    hb[j] = p0;
    float e1 = fb[T + j];
    float e2 = fb[2 * T + j];
    __syncthreads();

#pragma unroll 1
    for (int s = 1; s < S; s++) {
        float ecur = e1;
        e1 = e2;
        int sf = s + 2 < S ? s + 2 : S - 1;  // clamp -> unconditional LDG
        e2 = fb[sf * T + j];

        const float4* pp =
            reinterpret_cast<const float4*>(part[(s - 1) & 1][h]);
        float4 v0 = pp[0];
        float m0 = v0.x + c[0];
        float m1 = v0.y + c[1];
        float m2 = v0.z + c[2];
        float m3 = v0.w + c[3];
#pragma unroll
        for (int q = 1; q < 32; q++) {
            float4 u = pp[q];
            m0 = fmaxf(m0, u.x + c[4 * q + 0]);
            m1 = fmaxf(m1, u.y + c[4 * q + 1]);
            m2 = fmaxf(m2, u.z + c[4 * q + 2]);
            m3 = fmaxf(m3, u.w + c[4 * q + 3]);
        }
        float np = fmaxf(fmaxf(m0, m1), fmaxf(m2, m3)) + ecur;
        part[s & 1][h][j] = np;
        hb[s * T + j] = np;
        __syncthreads();
    }
}

// monotonic float -> u32 key (order preserving for finite floats)
__device__ __forceinline__ unsigned fkey(float f) {
    unsigned u = __float_as_uint(f);
    return u ^ ((unsigned)((int)u >> 31) | 0x80000000u);
}

// first-index argmax over the warp's 4-per-lane keys; returns index to all.
// ONE warp-collective REDUX + 4 overlapping ballots.
__device__ __forceinline__ int warp_argmax4(unsigned k0, unsigned k1,
                                            unsigned k2, unsigned k3, int l) {
    unsigned ka = (k0 > k1) ? k0 : k1;
    unsigned kb = (k2 > k3) ? k2 : k3;
    unsigned lm = (ka > kb) ? ka : kb;
    unsigned g = __reduce_max_sync(0xffffffffu, lm);
    unsigned b0 = __ballot_sync(0xffffffffu, k0 == g);
    unsigned b1 = __ballot_sync(0xffffffffu, k1 == g);
    unsigned b2 = __ballot_sync(0xffffffffu, k2 == g);
    unsigned b3 = __ballot_sync(0xffffffffu, k3 == g);
    unsigned all = b0 | b1 | b2 | b3;
    int l0 = __ffs((int)all) - 1;           // smallest lane with a hit
    unsigned bit = 1u << l0;
    int c = (b0 & bit) ? 0 : (b1 & bit) ? 1 : (b2 & bit) ? 2 : 3;
    return 4 * l0 + c;                      // lexicographic first index
}

// ---------------------------------------------------------------------------
// Kernel 2: per-WARP traceback (frozen R12 configuration: grid 64 x 4 warps,
// 1 chain per warp, 4-slot cp.async ring, refill between consume and argmax).
// ---------------------------------------------------------------------------
__global__ __launch_bounds__(128, 1) void k_traceback(
    const float* __restrict__ feats, const float* __restrict__ trans,
    const void* __restrict__ mask, float* __restrict__ out) {
    const int tid = threadIdx.x;
    const int wid = tid >> 5;
    const int l = tid & 31;
    const int b = blockIdx.x * 4 + wid;

    extern __shared__ float smem[];
    float* sT = smem;                                  // [T][TB_PITCH]
    float* wring = smem + T * TB_PITCH + wid * 1024;   // 4 slots x 256 floats

    // cooperative transpose of trans into padded smem (one-time)
    for (int k = tid; k < T * T; k += 128) {
        int i = k >> 7;
        int jj = k & 127;
        sT[jj * TB_PITCH + i] = trans[k];
    }
    __syncthreads();

    // ---- per-warp length: lane l counts 16 consecutive mask entries ----
    const unsigned w0 = *(const unsigned*)mask;  // dtype signature
    int cnt = 0;
    if (w0 == 0x01010101u) {  // 1-byte bool
        const uint4* m16 = (const uint4*)((const unsigned char*)mask +
                                          (size_t)b * S + l * 16);
        uint4 v = *m16;
        cnt = __popc(v.x) + __popc(v.y) + __popc(v.z) + __popc(v.w);
    } else if (w0 == 0x3F800000u) {  // float32
        const float* mf = (const float*)mask + (size_t)b * S + l * 16;
#pragma unroll
        for (int t = 0; t < 16; t++) cnt += (mf[t] != 0.f);
    } else if (w0 == 0x3F803F80u || w0 == 0x3C003C00u) {  // bf16 / f16
        const unsigned short* mh =
            (const unsigned short*)mask + (size_t)b * S + l * 16;
#pragma unroll
        for (int t = 0; t < 16; t++) cnt += (mh[t] != 0);
    } else {  // int32 0/1
        const int* mi = (const int*)mask + (size_t)b * S + l * 16;
#pragma unroll
        for (int t = 0; t < 16; t++) cnt += (mi[t] != 0);
    }
    cnt = __reduce_add_sync(0xffffffffu, cnt);
    const int last_pos = cnt - 1;

    const float* hist_b = g_hist + (size_t)b * S * T;
    const float* feats_b = feats + (size_t)b * S * T;

    // ---- final pointer: argmax_i(hist[last_pos][i] + trans[i][STOP]) ----
    int pointer;
    {
        float4 h = reinterpret_cast<const float4*>(hist_b + last_pos * T)[l];
        float4 tr = reinterpret_cast<const float4*>(sT + STOPT * TB_PITCH)[l];
        unsigned k0 = fkey(h.x + tr.x), k1 = fkey(h.y + tr.y);
        unsigned k2 = fkey(h.z + tr.z), k3 = fkey(h.w + tr.w);
        pointer = warp_argmax4(k0, k1, k2, k3, l);
    }

    float* ob = out + (size_t)b * S;

    // positions past the sequence: zeros (matches zeroed back_points rows)
    for (int s = last_pos + 1 + l; s < S - 1; s += 32) ob[s] = 0.0f;
    if (l == 0) {
        ob[S - 1] = (float)pointer;
        ob[last_pos] = (float)pointer;
    }

    int ptr = pointer;
    const int s0 = last_pos - 1;
    if (s0 < 0) return;

    // ---- prologue: fill 4 ring slots (steps s0 .. s0-3) ----
#pragma unroll
    for (int k = 0; k < 4; k++) {
        int sp = s0 - k;
        if (sp < 0) sp = 0;
        __pipeline_memcpy_async(wring + k * 256 + 4 * l,
                                hist_b + sp * T + 4 * l, 16);
        __pipeline_memcpy_async(wring + k * 256 + 128 + 4 * l,
                                feats_b + (sp + 1) * T + 4 * l, 16);
        __pipeline_commit();
    }

    int slot = 0;
    for (int s = s0; s >= 0; --s) {
        // wait only for the oldest outstanding group (this slot's data)
        __pipeline_wait_prior(3);
        const float* sb = wring + slot * 256;
        float4 h = *reinterpret_cast<const float4*>(sb + 4 * l);
        // scalar e = feats[b][s+1][ptr]: uniform-address broadcast LDS
        float e = sb[128 + ptr];

        // refill this slot for step s-4 (ptr-independent addresses)
        int sp = s - 4;
        if (sp < 0) sp = 0;
        __pipeline_memcpy_async(wring + slot * 256 + 4 * l,
                                hist_b + sp * T + 4 * l, 16);
        __pipeline_memcpy_async(wring + slot * 256 + 128 + 4 * l,
                                feats_b + (sp + 1) * T + 4 * l, 16);
        __pipeline_commit();

        // trans[:, ptr] chunk from padded smem (LDS.128, conflict-free)
        float4 tc = reinterpret_cast<const float4*>(sT + ptr * TB_PITCH)[l];

        // exact replication of reference: (part + trans) + e, argmax first-idx
        unsigned k0 = fkey((h.x + tc.x) + e);
        unsigned k1 = fkey((h.y + tc.y) + e);
        unsigned k2 = fkey((h.z + tc.z) + e);
        unsigned k3 = fkey((h.w + tc.w) + e);
        ptr = warp_argmax4(k0, k1, k2, k3, l);
        if (l == 0) ob[s] = (float)ptr;

        slot = (slot + 1) & 3;
    }
}

// ---------------------------------------------------------------------------
extern "C" void kernel_launch(void* const* d_in, const int* in_sizes, int n_in,
                              void* d_out, int out_size) {
    // Identify inputs by element count:
    //   feats 16777216, transitions 16384, mask 131072
    const float* feats = nullptr;
    const void* mask = nullptr;
    const float* trans = nullptr;
    for (int i = 0; i < n_in; i++) {
        int n = in_sizes[i];
        if (n == B * S * T) feats = (const float*)d_in[i];
        else if (n == T * T) trans = (const float*)d_in[i];
        else mask = d_in[i];
    }
    float* out = (float*)d_out;
    (void)out_size;

    // smem: transT (67584 B) + 4 warps x 4 slots x 256 floats (16384 B)
    const int smem_tb = T * TB_PITCH * sizeof(float) + 4 * 4 * 256 * 4;
    cudaFuncSetAttribute(k_traceback,
                         cudaFuncAttributeMaxDynamicSharedMemorySize, smem_tb);

    k_forward<<<B / 2, 2 * T>>>(feats, trans);
    k_traceback<<<B / 4, T, smem_tb>>>(feats, trans, mask, out);
}

// round 14
// speedup vs baseline: 1.1125x; 1.1125x over previous
#include <cuda_runtime.h>
#include <cuda_pipeline_primitives.h>

#define B 256
#define S 512
#define T 128
#define STARTT 125
#define STOPT 126
#define TB_PITCH 132  // padded row pitch (floats) for smem transT

// 64MB part-history scratch: hist[b][s][t]
__device__ float g_hist[(size_t)B * S * T];

// ---------------------------------------------------------------------------
// Kernel 1: forward Viterbi max-plus recurrence. One block per batch
// (R9/R12 exact configuration — measured best at ~226 us, ~88% issue floor).
// ---------------------------------------------------------------------------
__global__ __launch_bounds__(128, 2) void k_forward(
    const float* __restrict__ feats, const float* __restrict__ trans) {
    const int b = blockIdx.x;
    const int j = threadIdx.x;

    float c[T];
#pragma unroll
    for (int i = 0; i < T; i++) c[i] = trans[i * T + j];

    __shared__ __align__(16) float part[2][T];

    const float* fb = feats + (size_t)b * S * T;
    float* hb = g_hist + (size_t)b * S * T;

    float p0 = fb[j] + c[STARTT];
    part[0][j] = p0;
    hb[j] = p0;
    float e1 = fb[T + j];
    float e2 = fb[2 * T + j];
    __syncthreads();

#pragma unroll 1
    for (int s = 1; s < S; s++) {
        float ecur = e1;
        e1 = e2;
        int sf = s + 2 < S ? s + 2 : S - 1;  // clamp -> unconditional LDG
        e2 = fb[sf * T + j];

        const float4* pp = reinterpret_cast<const float4*>(part[(s - 1) & 1]);
        float4 v0 = pp[0];
        float m0 = v0.x + c[0];
        float m1 = v0.y + c[1];
        float m2 = v0.z + c[2];
        float m3 = v0.w + c[3];
#pragma unroll
        for (int q = 1; q < 32; q++) {
            float4 u = pp[q];
            m0 = fmaxf(m0, u.x + c[4 * q + 0]);
            m1 = fmaxf(m1, u.y + c[4 * q + 1]);
            m2 = fmaxf(m2, u.z + c[4 * q + 2]);
            m3 = fmaxf(m3, u.w + c[4 * q + 3]);
        }
        float np = fmaxf(fmaxf(m0, m1), fmaxf(m2, m3)) + ecur;
        part[s & 1][j] = np;
        hb[s * T + j] = np;
        __syncthreads();
    }
}

// monotonic float -> u32 key (order preserving for finite floats)
__device__ __forceinline__ unsigned fkey(float f) {
    unsigned u = __float_as_uint(f);
    return u ^ ((unsigned)((int)u >> 31) | 0x80000000u);
}

// first-index argmax over the warp's 4-per-lane keys; returns index to all.
// ONE warp-collective REDUX + 4 overlapping ballots.
__device__ __forceinline__ int warp_argmax4(unsigned k0, unsigned k1,
                                            unsigned k2, unsigned k3, int l) {
    unsigned ka = (k0 > k1) ? k0 : k1;
    unsigned kb = (k2 > k3) ? k2 : k3;
    unsigned lm = (ka > kb) ? ka : kb;
    unsigned g = __reduce_max_sync(0xffffffffu, lm);
    unsigned b0 = __ballot_sync(0xffffffffu, k0 == g);
    unsigned b1 = __ballot_sync(0xffffffffu, k1 == g);
    unsigned b2 = __ballot_sync(0xffffffffu, k2 == g);
    unsigned b3 = __ballot_sync(0xffffffffu, k3 == g);
    unsigned all = b0 | b1 | b2 | b3;
    int l0 = __ffs((int)all) - 1;           // smallest lane with a hit
    unsigned bit = 1u << l0;
    int c = (b0 & bit) ? 0 : (b1 & bit) ? 1 : (b2 & bit) ? 2 : 3;
    return 4 * l0 + c;                      // lexicographic first index
}

// one traceback step: consume slot sb, update ptr, store
__device__ __forceinline__ int tb_step(const float* sb, const float* sT,
                                       int ptr, int l) {
    float4 h = *reinterpret_cast<const float4*>(sb + 4 * l);
    float e = sb[128 + ptr];  // uniform-address broadcast LDS
    float4 tc = reinterpret_cast<const float4*>(sT + ptr * TB_PITCH)[l];
    unsigned k0 = fkey((h.x + tc.x) + e);
    unsigned k1 = fkey((h.y + tc.y) + e);
    unsigned k2 = fkey((h.z + tc.z) + e);
    unsigned k3 = fkey((h.w + tc.w) + e);
    return warp_argmax4(k0, k1, k2, k3, l);
}

// ---------------------------------------------------------------------------
// Kernel 2: per-WARP traceback, grid 64 x 4 warps, 1 chain per warp.
// 8-slot cp.async ring in groups of 2 slots: ONE wait_prior + ONE commit per
// TWO chain-steps (the wait's ~60-90 cyc fixed cost was paid every step).
// ---------------------------------------------------------------------------
__global__ __launch_bounds__(128, 1) void k_traceback(
    const float* __restrict__ feats, const float* __restrict__ trans,
    const void* __restrict__ mask, float* __restrict__ out) {
    const int tid = threadIdx.x;
    const int wid = tid >> 5;
    const int l = tid & 31;
    const int b = blockIdx.x * 4 + wid;

    extern __shared__ float smem[];
    float* sT = smem;                                  // [T][TB_PITCH]
    float* wring = smem + T * TB_PITCH + wid * 2048;   // 8 slots x 256 floats

    // cooperative transpose of trans into padded smem (one-time)
    for (int k = tid; k < T * T; k += 128) {
        int i = k >> 7;
        int jj = k & 127;
        sT[jj * TB_PITCH + i] = trans[k];
    }
    __syncthreads();

    // ---- per-warp length: lane l counts 16 consecutive mask entries ----
    const unsigned w0 = *(const unsigned*)mask;  // dtype signature
    int cnt = 0;
    if (w0 == 0x01010101u) {  // 1-byte bool
        const uint4* m16 = (const uint4*)((const unsigned char*)mask +
                                          (size_t)b * S + l * 16);
        uint4 v = *m16;
        cnt = __popc(v.x) + __popc(v.y) + __popc(v.z) + __popc(v.w);
    } else if (w0 == 0x3F800000u) {  // float32
        const float* mf = (const float*)mask + (size_t)b * S + l * 16;
#pragma unroll
        for (int t = 0; t < 16; t++) cnt += (mf[t] != 0.f);
    } else if (w0 == 0x3F803F80u || w0 == 0x3C003C00u) {  // bf16 / f16
        const unsigned short* mh =
            (const unsigned short*)mask + (size_t)b * S + l * 16;
#pragma unroll
        for (int t = 0; t < 16; t++) cnt += (mh[t] != 0);
    } else {  // int32 0/1
        const int* mi = (const int*)mask + (size_t)b * S + l * 16;
#pragma unroll
        for (int t = 0; t < 16; t++) cnt += (mi[t] != 0);
    }
    cnt = __reduce_add_sync(0xffffffffu, cnt);
    const int last_pos = cnt - 1;

    const float* hist_b = g_hist + (size_t)b * S * T;
    const float* feats_b = feats + (size_t)b * S * T;

    // ---- final pointer: argmax_i(hist[last_pos][i] + trans[i][STOP]) ----
    int pointer;
    {
        float4 h = reinterpret_cast<const float4*>(hist_b + last_pos * T)[l];
        float4 tr = reinterpret_cast<const float4*>(sT + STOPT * TB_PITCH)[l];
        unsigned k0 = fkey(h.x + tr.x), k1 = fkey(h.y + tr.y);
        unsigned k2 = fkey(h.z + tr.z), k3 = fkey(h.w + tr.w);
        pointer = warp_argmax4(k0, k1, k2, k3, l);
    }

    float* ob = out + (size_t)b * S;

    // positions past the sequence: zeros (matches zeroed back_points rows)
    for (int s = last_pos + 1 + l; s < S - 1; s += 32) ob[s] = 0.0f;
    if (l == 0) {
        ob[S - 1] = (float)pointer;
        ob[last_pos] = (float)pointer;
    }

    int ptr = pointer;
    const int s0 = last_pos - 1;
    if (s0 < 0) return;

    // ---- prologue: fill 4 groups x 2 slots (steps s0 .. s0-7) ----
#pragma unroll
    for (int g = 0; g < 4; g++) {
#pragma unroll
        for (int u = 0; u < 2; u++) {
            int k = 2 * g + u;
            int sp = s0 - k;
            if (sp < 0) sp = 0;
            __pipeline_memcpy_async(wring + k * 256 + 4 * l,
                                    hist_b + sp * T + 4 * l, 16);
            __pipeline_memcpy_async(wring + k * 256 + 128 + 4 * l,
                                    feats_b + (sp + 1) * T + 4 * l, 16);
        }
        __pipeline_commit();
    }

    int slot = 0;
#pragma unroll 1
    for (int s = s0; s >= 0; s -= 2) {
        // one wait per TWO steps: oldest group (this slot pair) is complete
        __pipeline_wait_prior(3);

        // step A (position s)
        ptr = tb_step(wring + slot * 256, sT, ptr, l);
        if (l == 0) ob[s] = (float)ptr;

        // step B (position s-1), guarded
        if (s - 1 >= 0) {
            ptr = tb_step(wring + (slot + 1) * 256, sT, ptr, l);
            if (l == 0) ob[s - 1] = (float)ptr;
        }

        // refill both slots for steps s-8 / s-9 (clamped), ONE commit
        int spA = s - 8;  if (spA < 0) spA = 0;
        int spB = s - 9;  if (spB < 0) spB = 0;
        __pipeline_memcpy_async(wring + slot * 256 + 4 * l,
                                hist_b + spA * T + 4 * l, 16);
        __pipeline_memcpy_async(wring + slot * 256 + 128 + 4 * l,
                                feats_b + (spA + 1) * T + 4 * l, 16);
        __pipeline_memcpy_async(wring + (slot + 1) * 256 + 4 * l,
                                hist_b + spB * T + 4 * l, 16);
        __pipeline_memcpy_async(wring + (slot + 1) * 256 + 128 + 4 * l,
                                feats_b + (spB + 1) * T + 4 * l, 16);
        __pipeline_commit();

        slot = (slot + 2) & 7;
    }
}

// ---------------------------------------------------------------------------
extern "C" void kernel_launch(void* const* d_in, const int* in_sizes, int n_in,
                              void* d_out, int out_size) {
    // Identify inputs by element count:
    //   feats 16777216, transitions 16384, mask 131072
    const float* feats = nullptr;
    const void* mask = nullptr;
    const float* trans = nullptr;
    for (int i = 0; i < n_in; i++) {
        int n = in_sizes[i];
        if (n == B * S * T) feats = (const float*)d_in[i];
        else if (n == T * T) trans = (const float*)d_in[i];
        else mask = d_in[i];
    }
    float* out = (float*)d_out;
    (void)out_size;

    // smem: transT (67584 B) + 4 warps x 8 slots x 256 floats (32768 B)
    const int smem_tb = T * TB_PITCH * sizeof(float) + 4 * 8 * 256 * 4;
    cudaFuncSetAttribute(k_traceback,
                         cudaFuncAttributeMaxDynamicSharedMemorySize, smem_tb);

    k_forward<<<B, T>>>(feats, trans);
    k_traceback<<<B / 4, T, smem_tb>>>(feats, trans, mask, out);
}

// round 15
// speedup vs baseline: 1.1191x; 1.0059x over previous
#include <cuda_runtime.h>
#include <cuda_pipeline_primitives.h>

#define B 256
#define S 512
#define T 128
#define STARTT 125
#define STOPT 126
#define TB_PITCH 132  // padded row pitch (floats) for smem transT

// 64MB part-history scratch: hist[b][s][t]
__device__ float g_hist[(size_t)B * S * T];

// ---------------------------------------------------------------------------
// Kernel 1: forward Viterbi max-plus recurrence. One block per batch
// (frozen R9/R12 configuration — ~226 us, ~90% of issue floor).
// ---------------------------------------------------------------------------
__global__ __launch_bounds__(128, 2) void k_forward(
    const float* __restrict__ feats, const float* __restrict__ trans) {
    const int b = blockIdx.x;
    const int j = threadIdx.x;

    float c[T];
#pragma unroll
    for (int i = 0; i < T; i++) c[i] = trans[i * T + j];

    __shared__ __align__(16) float part[2][T];

    const float* fb = feats + (size_t)b * S * T;
    float* hb = g_hist + (size_t)b * S * T;

    float p0 = fb[j] + c[STARTT];
    part[0][j] = p0;
    hb[j] = p0;
    float e1 = fb[T + j];
    float e2 = fb[2 * T + j];
    __syncthreads();

#pragma unroll 1
    for (int s = 1; s < S; s++) {
        float ecur = e1;
        e1 = e2;
        int sf = s + 2 < S ? s + 2 : S - 1;  // clamp -> unconditional LDG
        e2 = fb[sf * T + j];

        const float4* pp = reinterpret_cast<const float4*>(part[(s - 1) & 1]);
        float4 v0 = pp[0];
        float m0 = v0.x + c[0];
        float m1 = v0.y + c[1];
        float m2 = v0.z + c[2];
        float m3 = v0.w + c[3];
#pragma unroll
        for (int q = 1; q < 32; q++) {
            float4 u = pp[q];
            m0 = fmaxf(m0, u.x + c[4 * q + 0]);
            m1 = fmaxf(m1, u.y + c[4 * q + 1]);
            m2 = fmaxf(m2, u.z + c[4 * q + 2]);
            m3 = fmaxf(m3, u.w + c[4 * q + 3]);
        }
        float np = fmaxf(fmaxf(m0, m1), fmaxf(m2, m3)) + ecur;
        part[s & 1][j] = np;
        hb[s * T + j] = np;
        __syncthreads();
    }
}

// monotonic float -> u32 key (order preserving for finite floats)
__device__ __forceinline__ unsigned fkey(float f) {
    unsigned u = __float_as_uint(f);
    return u ^ ((unsigned)((int)u >> 31) | 0x80000000u);
}
// inverse of fkey
__device__ __forceinline__ float unfkey(unsigned k) {
    unsigned u = (k & 0x80000000u) ? (k ^ 0x80000000u) : ~k;
    return __uint_as_float(u);
}

// first-index argmax of the warp's 4-per-lane values (q0..q3 per lane).
// Chain: fmaxf tree -> 1 fkey -> REDUX.MAX -> unfkey -> 4 parallel ballots.
__device__ __forceinline__ int warp_argmax4f(float q0, float q1, float q2,
                                             float q3) {
    float ma = fmaxf(q0, q1);
    float mb = fmaxf(q2, q3);
    float ml = fmaxf(ma, mb);
    unsigned g = __reduce_max_sync(0xffffffffu, fkey(ml));
    float gf = unfkey(g);  // exact bit pattern of the global max
    unsigned b0 = __ballot_sync(0xffffffffu, q0 == gf);
    unsigned b1 = __ballot_sync(0xffffffffu, q1 == gf);
    unsigned b2 = __ballot_sync(0xffffffffu, q2 == gf);
    unsigned b3 = __ballot_sync(0xffffffffu, q3 == gf);
    unsigned all = b0 | b1 | b2 | b3;
    int l0 = __ffs((int)all) - 1;  // smallest lane with a hit
    unsigned bit = 1u << l0;
    int c = (b0 & bit) ? 0 : (b1 & bit) ? 1 : (b2 & bit) ? 2 : 3;
    return 4 * l0 + c;  // lexicographic first index
}

// one traceback step: consume slot sb, update ptr
__device__ __forceinline__ int tb_step(const float* sb, const float* sT,
                                       int ptr, int l) {
    float4 h = *reinterpret_cast<const float4*>(sb + 4 * l);
    float e = sb[128 + ptr];  // uniform-address broadcast LDS
    float4 tc = reinterpret_cast<const float4*>(sT + ptr * TB_PITCH)[l];
    float q0 = (h.x + tc.x) + e;
    float q1 = (h.y + tc.y) + e;
    float q2 = (h.z + tc.z) + e;
    float q3 = (h.w + tc.w) + e;
    return warp_argmax4f(q0, q1, q2, q3);
}

// ---------------------------------------------------------------------------
// Kernel 2: per-WARP traceback, grid 64 x 4 warps, 1 chain per warp.
// 16-slot cp.async ring in groups of 4: ONE wait_prior + ONE commit per FOUR
// chain-steps (R14 proved the per-iteration wait overhead is the lever).
// ---------------------------------------------------------------------------
__global__ __launch_bounds__(128, 1) void k_traceback(
    const float* __restrict__ feats, const float* __restrict__ trans,
    const void* __restrict__ mask, float* __restrict__ out) {
    const int tid = threadIdx.x;
    const int wid = tid >> 5;
    const int l = tid & 31;
    const int b = blockIdx.x * 4 + wid;

    extern __shared__ float smem[];
    float* sT = smem;                                  // [T][TB_PITCH]
    float* wring = smem + T * TB_PITCH + wid * 4096;   // 16 slots x 256 floats

    // cooperative transpose of trans into padded smem (one-time)
    for (int k = tid; k < T * T; k += 128) {
        int i = k >> 7;
        int jj = k & 127;
        sT[jj * TB_PITCH + i] = trans[k];
    }
    __syncthreads();

    // ---- per-warp length: lane l counts 16 consecutive mask entries ----
    const unsigned w0 = *(const unsigned*)mask;  // dtype signature
    int cnt = 0;
    if (w0 == 0x01010101u) {  // 1-byte bool
        const uint4* m16 = (const uint4*)((const unsigned char*)mask +
                                          (size_t)b * S + l * 16);
        uint4 v = *m16;
        cnt = __popc(v.x) + __popc(v.y) + __popc(v.z) + __popc(v.w);
    } else if (w0 == 0x3F800000u) {  // float32
        const float* mf = (const float*)mask + (size_t)b * S + l * 16;
#pragma unroll
        for (int t = 0; t < 16; t++) cnt += (mf[t] != 0.f);
    } else if (w0 == 0x3F803F80u || w0 == 0x3C003C00u) {  // bf16 / f16
        const unsigned short* mh =
            (const unsigned short*)mask + (size_t)b * S + l * 16;
#pragma unroll
        for (int t = 0; t < 16; t++) cnt += (mh[t] != 0);
    } else {  // int32 0/1
        const int* mi = (const int*)mask + (size_t)b * S + l * 16;
#pragma unroll
        for (int t = 0; t < 16; t++) cnt += (mi[t] != 0);
    }
    cnt = __reduce_add_sync(0xffffffffu, cnt);
    const int last_pos = cnt - 1;

    const float* hist_b = g_hist + (size_t)b * S * T;
    const float* feats_b = feats + (size_t)b * S * T;

    // ---- final pointer: argmax_i(hist[last_pos][i] + trans[i][STOP]) ----
    int pointer;
    {
        float4 h = reinterpret_cast<const float4*>(hist_b + last_pos * T)[l];
        float4 tr = reinterpret_cast<const float4*>(sT + STOPT * TB_PITCH)[l];
        pointer = warp_argmax4f(h.x + tr.x, h.y + tr.y, h.z + tr.z,
                                h.w + tr.w);
    }

    float* ob = out + (size_t)b * S;

    // positions past the sequence: zeros (matches zeroed back_points rows)
    for (int s = last_pos + 1 + l; s < S - 1; s += 32) ob[s] = 0.0f;
    if (l == 0) {
        ob[S - 1] = (float)pointer;
        ob[last_pos] = (float)pointer;
    }

    int ptr = pointer;
    const int s0 = last_pos - 1;
    if (s0 < 0) return;

    // ---- prologue: fill 4 groups x 4 slots (steps s0 .. s0-15) ----
#pragma unroll
    for (int g = 0; g < 4; g++) {
#pragma unroll
        for (int u = 0; u < 4; u++) {
            int k = 4 * g + u;
            int sp = s0 - k;
            if (sp < 0) sp = 0;
            __pipeline_memcpy_async(wring + k * 256 + 4 * l,
                                    hist_b + sp * T + 4 * l, 16);
            __pipeline_memcpy_async(wring + k * 256 + 128 + 4 * l,
                                    feats_b + (sp + 1) * T + 4 * l, 16);
        }
        __pipeline_commit();
    }

    int slot = 0;
#pragma unroll 1
    for (int s = s0; s >= 0; s -= 4) {
        // one wait per FOUR steps: oldest group (this slot quad) is complete
        __pipeline_wait_prior(3);

#pragma unroll
        for (int u = 0; u < 4; u++) {
            if (s - u >= 0) {
                ptr = tb_step(wring + (slot + u) * 256, sT, ptr, l);
                if (l == 0) ob[s - u] = (float)ptr;
            }
        }

        // refill the quad for steps s-16 .. s-19 (clamped), ONE commit
#pragma unroll
        for (int u = 0; u < 4; u++) {
            int sp = s - 16 - u;
            if (sp < 0) sp = 0;
            __pipeline_memcpy_async(wring + (slot + u) * 256 + 4 * l,
                                    hist_b + sp * T + 4 * l, 16);
            __pipeline_memcpy_async(wring + (slot + u) * 256 + 128 + 4 * l,
                                    feats_b + (sp + 1) * T + 4 * l, 16);
        }
        __pipeline_commit();

        slot = (slot + 4) & 15;
    }
}

// ---------------------------------------------------------------------------
extern "C" void kernel_launch(void* const* d_in, const int* in_sizes, int n_in,
                              void* d_out, int out_size) {
    // Identify inputs by element count:
    //   feats 16777216, transitions 16384, mask 131072
    const float* feats = nullptr;
    const void* mask = nullptr;
    const float* trans = nullptr;
    for (int i = 0; i < n_in; i++) {
        int n = in_sizes[i];
        if (n == B * S * T) feats = (const float*)d_in[i];
        else if (n == T * T) trans = (const float*)d_in[i];
        else mask = d_in[i];
    }
    float* out = (float*)d_out;
    (void)out_size;

    // smem: transT (67584 B) + 4 warps x 16 slots x 1024 B (65536 B)
    const int smem_tb = T * TB_PITCH * sizeof(float) + 4 * 16 * 256 * 4;
    cudaFuncSetAttribute(k_traceback,
                         cudaFuncAttributeMaxDynamicSharedMemorySize, smem_tb);

    k_forward<<<B, T>>>(feats, trans);
    k_traceback<<<B / 4, T, smem_tb>>>(feats, trans, mask, out);
}

// round 16
// speedup vs baseline: 1.1207x; 1.0015x over previous
#include <cuda_runtime.h>
#include <cuda_pipeline_primitives.h>

#define B 256
#define S 512
#define T 128
#define STARTT 125
#define STOPT 126
#define TB_PITCH 132  // padded row pitch (floats) for smem transT

// 64MB part-history scratch: hist[b][s][t]
__device__ float g_hist[(size_t)B * S * T];

// 3-input max (PTX ISA 8.0+, sm_90+; SASS FMNMX3) — halves the max count
__device__ __forceinline__ float fmax3(float a, float b, float c) {
    float d;
    asm("max.f32 %0, %1, %2, %3;" : "=f"(d) : "f"(a), "f"(b), "f"(c));
    return d;
}

// ---------------------------------------------------------------------------
// Kernel 1: forward Viterbi max-plus recurrence. One block per batch.
// Thread j holds trans[:, j] in 128 registers. Inner loop per 4 "from"
// states: 1 LDS.128 + 4 FADD + 2 FMNMX3 (~228 issues/warp/step, was 290).
// ---------------------------------------------------------------------------
__global__ __launch_bounds__(128, 2) void k_forward(
    const float* __restrict__ feats, const float* __restrict__ trans) {
    const int b = blockIdx.x;
    const int j = threadIdx.x;

    float c[T];
#pragma unroll
    for (int i = 0; i < T; i++) c[i] = trans[i * T + j];

    __shared__ __align__(16) float part[2][T];

    const float* fb = feats + (size_t)b * S * T;
    float* hb = g_hist + (size_t)b * S * T;

    float p0 = fb[j] + c[STARTT];
    part[0][j] = p0;
    hb[j] = p0;
    float e1 = fb[T + j];
    float e2 = fb[2 * T + j];
    __syncthreads();

#pragma unroll 1
    for (int s = 1; s < S; s++) {
        float ecur = e1;
        e1 = e2;
        int sf = s + 2 < S ? s + 2 : S - 1;  // clamp -> unconditional LDG
        e2 = fb[sf * T + j];

        const float4* pp = reinterpret_cast<const float4*>(part[(s - 1) & 1]);
        float4 v0 = pp[0];
        float m0 = fmaxf(v0.x + c[0], v0.y + c[1]);
        float m1 = fmaxf(v0.z + c[2], v0.w + c[3]);
#pragma unroll
        for (int q = 1; q < 32; q++) {
            float4 u = pp[q];
            float s0 = u.x + c[4 * q + 0];
            float s1 = u.y + c[4 * q + 1];
            float s2 = u.z + c[4 * q + 2];
            float s3 = u.w + c[4 * q + 3];
            m0 = fmax3(m0, s0, s1);
            m1 = fmax3(m1, s2, s3);
        }
        float np = fmaxf(m0, m1) + ecur;
        part[s & 1][j] = np;
        hb[s * T + j] = np;
        __syncthreads();
    }
}

// monotonic float -> u32 key (order preserving for finite floats)
__device__ __forceinline__ unsigned fkey(float f) {
    unsigned u = __float_as_uint(f);
    return u ^ ((unsigned)((int)u >> 31) | 0x80000000u);
}
// inverse of fkey
__device__ __forceinline__ float unfkey(unsigned k) {
    unsigned u = (k & 0x80000000u) ? (k ^ 0x80000000u) : ~k;
    return __uint_as_float(u);
}

// first-index argmax of the warp's 4-per-lane values (q0..q3 per lane).
__device__ __forceinline__ int warp_argmax4f(float q0, float q1, float q2,
                                             float q3) {
    float ma = fmaxf(q0, q1);
    float mb = fmaxf(q2, q3);
    float ml = fmaxf(ma, mb);
    unsigned g = __reduce_max_sync(0xffffffffu, fkey(ml));
    float gf = unfkey(g);  // exact bit pattern of the global max
    unsigned b0 = __ballot_sync(0xffffffffu, q0 == gf);
    unsigned b1 = __ballot_sync(0xffffffffu, q1 == gf);
    unsigned b2 = __ballot_sync(0xffffffffu, q2 == gf);
    unsigned b3 = __ballot_sync(0xffffffffu, q3 == gf);
    unsigned all = b0 | b1 | b2 | b3;
    int l0 = __ffs((int)all) - 1;  // smallest lane with a hit
    unsigned bit = 1u << l0;
    int c = (b0 & bit) ? 0 : (b1 & bit) ? 1 : (b2 & bit) ? 2 : 3;
    return 4 * l0 + c;  // lexicographic first index
}

// one traceback step: consume slot sb, update ptr
__device__ __forceinline__ int tb_step(const float* sb, const float* sT,
                                       int ptr, int l) {
    float4 h = *reinterpret_cast<const float4*>(sb + 4 * l);
    float e = sb[128 + ptr];  // uniform-address broadcast LDS
    float4 tc = reinterpret_cast<const float4*>(sT + ptr * TB_PITCH)[l];
    float q0 = (h.x + tc.x) + e;
    float q1 = (h.y + tc.y) + e;
    float q2 = (h.z + tc.z) + e;
    float q3 = (h.w + tc.w) + e;
    return warp_argmax4f(q0, q1, q2, q3);
}

// ---------------------------------------------------------------------------
// Kernel 2: per-WARP traceback (frozen R15 configuration: grid 64 x 4 warps,
// 1 chain per warp, 16-slot cp.async ring, one wait/commit per 4 steps).
// ---------------------------------------------------------------------------
__global__ __launch_bounds__(128, 1) void k_traceback(
    const float* __restrict__ feats, const float* __restrict__ trans,
    const void* __restrict__ mask, float* __restrict__ out) {
    const int tid = threadIdx.x;
    const int wid = tid >> 5;
    const int l = tid & 31;
    const int b = blockIdx.x * 4 + wid;

    extern __shared__ float smem[];
    float* sT = smem;                                  // [T][TB_PITCH]
    float* wring = smem + T * TB_PITCH + wid * 4096;   // 16 slots x 256 floats

    // cooperative transpose of trans into padded smem (one-time)
    for (int k = tid; k < T * T; k += 128) {
        int i = k >> 7;
        int jj = k & 127;
        sT[jj * TB_PITCH + i] = trans[k];
    }
    __syncthreads();

    // ---- per-warp length: lane l counts 16 consecutive mask entries ----
    const unsigned w0 = *(const unsigned*)mask;  // dtype signature
    int cnt = 0;
    if (w0 == 0x01010101u) {  // 1-byte bool
        const uint4* m16 = (const uint4*)((const unsigned char*)mask +
                                          (size_t)b * S + l * 16);
        uint4 v = *m16;
        cnt = __popc(v.x) + __popc(v.y) + __popc(v.z) + __popc(v.w);
    } else if (w0 == 0x3F800000u) {  // float32
        const float* mf = (const float*)mask + (size_t)b * S + l * 16;
#pragma unroll
        for (int t = 0; t < 16; t++) cnt += (mf[t] != 0.f);
    } else if (w0 == 0x3F803F80u || w0 == 0x3C003C00u) {  // bf16 / f16
        const unsigned short* mh =
            (const unsigned short*)mask + (size_t)b * S + l * 16;
#pragma unroll
        for (int t = 0; t < 16; t++) cnt += (mh[t] != 0);
    } else {  // int32 0/1
        const int* mi = (const int*)mask + (size_t)b * S + l * 16;
#pragma unroll
        for (int t = 0; t < 16; t++) cnt += (mi[t] != 0);
    }
    cnt = __reduce_add_sync(0xffffffffu, cnt);
    const int last_pos = cnt - 1;

    const float* hist_b = g_hist + (size_t)b * S * T;
    const float* feats_b = feats + (size_t)b * S * T;

    // ---- final pointer: argmax_i(hist[last_pos][i] + trans[i][STOP]) ----
    int pointer;
    {
        float4 h = reinterpret_cast<const float4*>(hist_b + last_pos * T)[l];
        float4 tr = reinterpret_cast<const float4*>(sT + STOPT * TB_PITCH)[l];
        pointer = warp_argmax4f(h.x + tr.x, h.y + tr.y, h.z + tr.z,
                                h.w + tr.w);
    }

    float* ob = out + (size_t)b * S;

    // positions past the sequence: zeros (matches zeroed back_points rows)
    for (int s = last_pos + 1 + l; s < S - 1; s += 32) ob[s] = 0.0f;
    if (l == 0) {
        ob[S - 1] = (float)pointer;
        ob[last_pos] = (float)pointer;
    }

    int ptr = pointer;
    const int s0 = last_pos - 1;
    if (s0 < 0) return;

    // ---- prologue: fill 4 groups x 4 slots (steps s0 .. s0-15) ----
#pragma unroll
    for (int g = 0; g < 4; g++) {
#pragma unroll
        for (int u = 0; u < 4; u++) {
            int k = 4 * g + u;
            int sp = s0 - k;
            if (sp < 0) sp = 0;
            __pipeline_memcpy_async(wring + k * 256 + 4 * l,
                                    hist_b + sp * T + 4 * l, 16);
            __pipeline_memcpy_async(wring + k * 256 + 128 + 4 * l,
                                    feats_b + (sp + 1) * T + 4 * l, 16);
        }
        __pipeline_commit();
    }

    int slot = 0;
#pragma unroll 1
    for (int s = s0; s >= 0; s -= 4) {
        // one wait per FOUR steps: oldest group (this slot quad) is complete
        __pipeline_wait_prior(3);

#pragma unroll
        for (int u = 0; u < 4; u++) {
            if (s - u >= 0) {
                ptr = tb_step(wring + (slot + u) * 256, sT, ptr, l);
                if (l == 0) ob[s - u] = (float)ptr;
            }
        }

        // refill the quad for steps s-16 .. s-19 (clamped), ONE commit
#pragma unroll
        for (int u = 0; u < 4; u++) {
            int sp = s - 16 - u;
            if (sp < 0) sp = 0;
            __pipeline_memcpy_async(wring + (slot + u) * 256 + 4 * l,
                                    hist_b + sp * T + 4 * l, 16);
            __pipeline_memcpy_async(wring + (slot + u) * 256 + 128 + 4 * l,
                                    feats_b + (sp + 1) * T + 4 * l, 16);
        }
        __pipeline_commit();

        slot = (slot + 4) & 15;
    }
}

// ---------------------------------------------------------------------------
extern "C" void kernel_launch(void* const* d_in, const int* in_sizes, int n_in,
                              void* d_out, int out_size) {
    // Identify inputs by element count:
    //   feats 16777216, transitions 16384, mask 131072
    const float* feats = nullptr;
    const void* mask = nullptr;
    const float* trans = nullptr;
    for (int i = 0; i < n_in; i++) {
        int n = in_sizes[i];
        if (n == B * S * T) feats = (const float*)d_in[i];
        else if (n == T * T) trans = (const float*)d_in[i];
        else mask = d_in[i];
    }
    float* out = (float*)d_out;
    (void)out_size;

    // smem: transT (67584 B) + 4 warps x 16 slots x 1024 B (65536 B)
    const int smem_tb = T * TB_PITCH * sizeof(float) + 4 * 16 * 256 * 4;
    cudaFuncSetAttribute(k_traceback,
                         cudaFuncAttributeMaxDynamicSharedMemorySize, smem_tb);

    k_forward<<<B, T>>>(feats, trans);
    k_traceback<<<B / 4, T, smem_tb>>>(feats, trans, mask, out);
}